// round 13
// baseline (speedup 1.0000x reference)
#include <cuda_runtime.h>
#include <cstdint>

#define NB 8
#define NQ 100000
#define NC 10
#define NPB (NQ*NC)          // 1,000,000 logits per batch
#define NP 20
#define TOPK 100
#define CAP 32768
#define KEY0 0xC0400000u     // sortable key of +3.0f (speculative threshold)
#define SHC 2048             // shared candidate cache
#define ARRC 1024            // filtered set cap (fast rank path)
#define FBLK 512

// ---- scratch (zero-initialized; final_k resets for graph replay) ----
__device__ int                g_cnt[NB];
__device__ unsigned long long g_cand[NB][CAP];

__device__ __forceinline__ unsigned int f2key(float f) {
    unsigned int u = __float_as_uint(f);
    return (u & 0x80000000u) ? ~u : (u | 0x80000000u);
}
__device__ __forceinline__ float key2f(unsigned int k) {
    unsigned int u = (k & 0x80000000u) ? (k & 0x7FFFFFFFu) : ~k;
    return __uint_as_float(u);
}
__device__ __forceinline__ void push_cand(int b, unsigned int key, unsigned int lidx) {
    int pos = atomicAdd(&g_cnt[b], 1);
    if (pos < CAP)
        g_cand[b][pos] = ((unsigned long long)key << 32) | (unsigned int)(~lidx);
}

// ---- Pass 1: streaming scan, 8 loads in flight per thread (R8-measured ~9us) ----
#define SCAN_BLOCKS 977
#define SCAN_THREADS (SCAN_BLOCKS * 256)   // 250112 >= 2,000,000/8

__device__ __forceinline__ void proc4(float4 v, unsigned int i /*float4 idx*/) {
    unsigned int k0 = f2key(v.x), k1 = f2key(v.y), k2 = f2key(v.z), k3 = f2key(v.w);
    if ((k0 >= KEY0) | (k1 >= KEY0) | (k2 >= KEY0) | (k3 >= KEY0)) {
        int b = (int)(i / (NPB / 4));
        unsigned int e = i * 4u - (unsigned int)b * (unsigned int)NPB;
        if (k0 >= KEY0) push_cand(b, k0, e + 0);
        if (k1 >= KEY0) push_cand(b, k1, e + 1);
        if (k2 >= KEY0) push_cand(b, k2, e + 2);
        if (k3 >= KEY0) push_cand(b, k3, e + 3);
    }
}

__global__ void scan_k(const float* __restrict__ cls) {
    const float4* src = (const float4*)cls;
    const unsigned int n4 = (unsigned int)NB * (NPB / 4);   // 2,000,000
    const unsigned int S = SCAN_THREADS;
    const unsigned int t = blockIdx.x * blockDim.x + threadIdx.x;
    float4 v[8];
    bool ok[8];
#pragma unroll
    for (int j = 0; j < 8; j++) {
        unsigned int i = t + (unsigned int)j * S;
        ok[j] = (i < n4);
        if (ok[j]) v[j] = __ldcs(src + i);
    }
#pragma unroll
    for (int j = 0; j < 8; j++)
        if (ok[j]) proc4(v[j], t + (unsigned int)j * S);
}

// suffix-inclusive count at bin tid, via warp shuffles. blockDim.x == 512.
__device__ __forceinline__ unsigned int suffix_of(unsigned int cntv, unsigned int* wsum) {
    const int tid = threadIdx.x, lane = tid & 31, wid = tid >> 5;
    unsigned int v = cntv;
#pragma unroll
    for (int off = 1; off < 32; off <<= 1) {
        unsigned int u = __shfl_down_sync(0xFFFFFFFFu, v, off);
        if (lane + off < 32) v += u;
    }
    if (lane == 0) wsum[wid] = v;   // warp total
    __syncthreads();
    if (tid < 16) {
        unsigned int w = wsum[tid];
#pragma unroll
        for (int off = 1; off < 16; off <<= 1) {
            unsigned int u = __shfl_down_sync(0xFFFFu, w, off);
            if (tid + off < 16) w += u;
        }
        wsum[tid] = w;              // inclusive suffix over warp totals
    }
    __syncthreads();
    return v + ((wid < 15) ? wsum[wid + 1] : 0u);
}

// ---- Pass 2: fast finisher (R12-measured ~3us as fused tail), 8 blocks ----
__global__ void __launch_bounds__(FBLK) final_k(const float* __restrict__ cls,
                                                const float* __restrict__ bbox,
                                                const float* __restrict__ pts,
                                                float* __restrict__ out) {
    __shared__ unsigned long long shcand[SHC];     // 16KB (aliased as fallback hist)
    __shared__ unsigned long long arr[ARRC];       // 8KB filtered set
    __shared__ unsigned long long topc[TOPK];
    __shared__ unsigned int hcnt[512];
    __shared__ unsigned int wsum[16];
    __shared__ unsigned int cut_s;
    __shared__ int nkeep, mode_s;
    __shared__ float thr_s;
    __shared__ int   qA[TOPK];
    __shared__ unsigned char mA[TOPK];

    const int b = blockIdx.x;
    const int tid = threadIdx.x;

    int cnt = g_cnt[b];
    if (cnt < TOPK || cnt > CAP) {
        // ---- cold fallback (never taken on this data): exact recollect ----
        unsigned int* h4 = (unsigned int*)shcand;          // 4096 bins
        if (tid == 0) g_cnt[b] = 0;
        for (int t = tid; t < 4096; t += FBLK) h4[t] = 0u;
        __syncthreads();
        const float* basep = cls + (size_t)b * NPB;
        for (int i = tid; i < NPB; i += FBLK)
            atomicAdd(&h4[f2key(basep[i]) >> 20], 1u);
        __syncthreads();
        if (tid == 0) {
            unsigned int acc = 0; int cut = 0;
            for (int t = 4095; t >= 0; t--) { acc += h4[t]; if (acc >= TOPK) { cut = t; break; } }
            cut_s = (unsigned int)cut << 20;
        }
        __syncthreads();
        unsigned int ckf = cut_s;
        for (int i = tid; i < NPB; i += FBLK) {
            unsigned int key = f2key(basep[i]);
            if (key >= ckf) push_cand(b, key, (unsigned int)i);
        }
        __syncthreads();
        cnt = min(g_cnt[b], CAP);
        __syncthreads();
    }
    cnt = min(cnt, CAP);

    // cache candidates in shared (single global read)
    const unsigned long long* gc = g_cand[b];
    const bool cached = (cnt <= SHC);
    if (cached) {
        for (int i = tid; i < cnt; i += FBLK) shcand[i] = gc[i];
        __syncthreads();
    }
    const unsigned long long* cand = cached ? (const unsigned long long*)shcand : gc;

    // ---- level 1: 512-bin cut on key>>23 ----
    hcnt[tid] = 0u;
    __syncthreads();
    for (int i = tid; i < cnt; i += FBLK)
        atomicAdd(&hcnt[(unsigned int)(cand[i] >> (32 + 23))], 1u);
    __syncthreads();
    {
        unsigned int cv = hcnt[tid];
        unsigned int s = suffix_of(cv, wsum);
        if (s >= TOPK && s - cv < TOPK) cut_s = (unsigned int)tid;
    }
    __syncthreads();
    const unsigned int basek = cut_s << 23;
    __syncthreads();

    // ---- level 2: 512 bins of width 2^14 ----
    hcnt[tid] = 0u;
    __syncthreads();
    for (int i = tid; i < cnt; i += FBLK) {
        unsigned int key = (unsigned int)(cand[i] >> 32);
        if (key >= basek) atomicAdd(&hcnt[min(511u, (key - basek) >> 14)], 1u);
    }
    __syncthreads();
    {
        unsigned int cv = hcnt[tid];
        unsigned int s = suffix_of(cv, wsum);
        if (s >= TOPK && s - cv < TOPK) cut_s = (unsigned int)tid;
    }
    __syncthreads();
    const unsigned int ck = basek + (cut_s << 14);

    // ---- filter >= ck into shared arr ----
    if (tid == 0) nkeep = 0;
    __syncthreads();
    for (int i = tid; i < cnt; i += FBLK) {
        unsigned long long c = cand[i];
        if ((unsigned int)(c >> 32) >= ck) {
            int p = atomicAdd(&nkeep, 1);
            if (p < ARRC) arr[p] = c;
        }
    }
    __syncthreads();
    const int n = nkeep;

    // ---- exact rank-by-count (composites distinct -> unique ranks) ----
    if (tid < TOPK) topc[tid] = 0ULL;
    __syncthreads();
    if (n <= ARRC) {
        for (int i = tid; i < n; i += FBLK) {
            unsigned long long c = arr[i];
            int rank = 0;
            for (int j = 0; j < n; j++) rank += (arr[j] > c);
            if (rank < TOPK) topc[rank] = c;
        }
    } else {
        // degenerate ties overflow (never on this data): rank over full list
        for (int i = tid; i < cnt; i += FBLK) {
            unsigned long long c = cand[i];
            if ((unsigned int)(c >> 32) >= ck) {
                int rank = 0;
                for (int j = 0; j < cnt; j++) rank += (cand[j] > c);
                if (rank < TOPK) topc[rank] = c;
            }
        }
    }
    __syncthreads();

    if (tid == 0) {
        float f = key2f((unsigned int)(topc[0] >> 32));
        float maxs = 1.f / (1.f + expf(-f));
        int mode; float thr = 0.1f;
        if (maxs > 0.1f) mode = 0;
        else {
            float tmp = 0.1f; mode = 2;
            while (true) {
                tmp *= 0.9f;
                if (tmp < 0.01f) { mode = 2; break; }
                if (maxs >= tmp) { mode = 1; thr = tmp; break; }
            }
        }
        mode_s = mode; thr_s = thr;
    }
    __syncthreads();

    // output layout (float32, tuple order, C-contiguous each):
    float* oBox   = out;                       // [NB][TOPK][4]
    float* oScore = out + NB * TOPK * 4;       // [NB][TOPK]
    float* oLabel = oScore + NB * TOPK;        // [NB][TOPK]
    float* oPts   = oLabel + NB * TOPK;        // [NB][TOPK][NP][2]
    float* oMask  = oPts + NB * TOPK * NP * 2; // [NB][TOPK]

    // ---- stage 1: per-rank metadata + box/score/label/mask writes ----
    if (tid < TOPK) {
        const int r = tid;
        unsigned long long c = topc[r];
        const bool valid = (r < n);
        float score = 0.f, x1 = 0.f, y1 = 0.f, x2 = 0.f, y2 = 0.f;
        int label = 0, q = 0;
        bool mask = false;
        if (valid) {
            unsigned int key = (unsigned int)(c >> 32);
            unsigned int idx = ~(unsigned int)(c & 0xFFFFFFFFu);
            float f = key2f(key);
            score = 1.f / (1.f + expf(-f));
            label = (int)(idx % NC);
            q     = (int)(idx / NC);
            const float4 bb = __ldg((const float4*)(bbox + ((size_t)b * NQ + q) * 4));
            float cx = bb.x, cy = bb.y, w = bb.z, h = bb.w;
            x1 = (cx - w * 0.5f) * 30.f - 15.f;
            y1 = (cy - h * 0.5f) * 60.f - 30.f;
            x2 = (cx + w * 0.5f) * 30.f - 15.f;
            y2 = (cy + h * 0.5f) * 60.f - 30.f;
            bool rmask = x1 >= -20.f && y1 >= -35.f && x2 >= -20.f && y2 >= -35.f
                      && x1 <=  20.f && y1 <=  35.f && x2 <=  20.f && y2 <=  35.f;
            bool tm = (mode_s == 0) ? (score > 0.1f)
                    : (mode_s == 1) ? (score >= thr_s) : true;
            mask = rmask && tm;
        }
        qA[r] = q;
        mA[r] = mask ? 1 : 0;
        const size_t ob = (size_t)b * TOPK + r;
        ((float4*)oBox)[ob] = mask ? make_float4(x1, y1, x2, y2)
                                   : make_float4(0.f, 0.f, 0.f, 0.f);
        oScore[ob] = mask ? score : 0.f;
        oLabel[ob] = mask ? (float)label : 0.f;
        oMask[ob]  = mask ? 1.f : 0.f;
    }
    __syncthreads();

    // ---- stage 2: pts gather, vectorized and spread over all threads ----
    // 100 rows x 10 float4 chunks (40 floats per row)
    for (int t = tid; t < TOPK * 10; t += FBLK) {
        const int r = t / 10, c4 = t % 10;
        const bool mk = mA[r] != 0;
        float4 o = make_float4(0.f, 0.f, 0.f, 0.f);
        if (mk) {
            const float4 v = __ldg((const float4*)(pts + ((size_t)b * NQ + qA[r]) * (NP * 2)) + c4);
            o.x = v.x * 30.f - 15.f;
            o.y = v.y * 60.f - 30.f;
            o.z = v.z * 30.f - 15.f;
            o.w = v.w * 60.f - 30.f;
        }
        ((float4*)oPts)[(size_t)b * TOPK * 10 + t] = o;
    }

    // ---- reset scratch for next graph replay (after all reads) ----
    __syncthreads();
    if (tid == 0) g_cnt[b] = 0;
}

extern "C" void kernel_launch(void* const* d_in, const int* in_sizes, int n_in,
                              void* d_out, int out_size) {
    const float* cls  = (const float*)d_in[0];   // [8,100000,10]
    const float* bbox = (const float*)d_in[1];   // [8,100000,4]
    const float* pts  = (const float*)d_in[2];   // [8,100000,20,2]
    float* out = (float*)d_out;

    scan_k<<<SCAN_BLOCKS, 256>>>(cls);
    final_k<<<NB, FBLK>>>(cls, bbox, pts, out);
}

// round 14
// speedup vs baseline: 1.2698x; 1.2698x over previous
#include <cuda_runtime.h>
#include <cstdint>

#define NB 8
#define NQ 100000
#define NC 10
#define NPB (NQ*NC)          // 1,000,000 logits per batch
#define N4B (NPB/4)          // 250,000 float4 per batch
#define NP 20
#define TOPK 100
#define CAP 32768
#define KEY0 0xC0400000u     // sortable key of +3.0f (speculative threshold)
#define BLK 512
#define F4_PER_BLK 4096      // BLK * 8
#define BLK_PER_B 62         // 62*4096 = 253952 >= 250000
#define LQ 256               // per-block local candidate queue (expected ~22)
#define SHC 2048             // shared candidate cache
#define ARRC 1024            // filtered set cap (fast rank path)

// ---- scratch (zero-initialized; finisher resets for graph replay) ----
__device__ int                g_cnt[NB];
__device__ int                g_done[NB];
__device__ int                g_ovf[NB];
__device__ unsigned long long g_cand[NB][CAP];

__device__ __forceinline__ unsigned int f2key(float f) {
    unsigned int u = __float_as_uint(f);
    return (u & 0x80000000u) ? ~u : (u | 0x80000000u);
}
__device__ __forceinline__ float key2f(unsigned int k) {
    unsigned int u = (k & 0x80000000u) ? (k & 0x7FFFFFFFu) : ~k;
    return __uint_as_float(u);
}

// suffix-inclusive count at bin tid, via warp shuffles. blockDim.x == 512.
__device__ __forceinline__ unsigned int suffix_of(unsigned int cntv, unsigned int* wsum) {
    const int tid = threadIdx.x, lane = tid & 31, wid = tid >> 5;
    unsigned int v = cntv;
#pragma unroll
    for (int off = 1; off < 32; off <<= 1) {
        unsigned int u = __shfl_down_sync(0xFFFFFFFFu, v, off);
        if (lane + off < 32) v += u;
    }
    if (lane == 0) wsum[wid] = v;   // warp total
    __syncthreads();
    if (tid < 16) {
        unsigned int w = wsum[tid];
#pragma unroll
        for (int off = 1; off < 16; off <<= 1) {
            unsigned int u = __shfl_down_sync(0xFFFFu, w, off);
            if (tid + off < 16) w += u;
        }
        wsum[tid] = w;              // inclusive suffix over warp totals
    }
    __syncthreads();
    return v + ((wid < 15) ? wsum[wid + 1] : 0u);
}

__global__ void __launch_bounds__(BLK) fused_k(const float* __restrict__ cls,
                                               const float* __restrict__ bbox,
                                               const float* __restrict__ pts,
                                               float* __restrict__ out) {
    const int b = blockIdx.y;
    const int tid = threadIdx.x;

    // shared: local candidate queue for the scan phase
    __shared__ unsigned long long lq[LQ];
    __shared__ int lqn;
    __shared__ int gbase;

    if (tid == 0) lqn = 0;
    __syncthreads();

    // ================= scan phase: local-queue collection =================
    {
        const float4* src = (const float4*)(cls + (size_t)b * NPB);
        const unsigned int base = blockIdx.x * F4_PER_BLK + tid;
#pragma unroll
        for (int g = 0; g < 2; g++) {
            float4 v[4]; bool ok[4];
#pragma unroll
            for (int j = 0; j < 4; j++) {
                unsigned int i = base + (unsigned int)(g * 4 + j) * BLK;
                ok[j] = (i < N4B);
                if (ok[j]) v[j] = __ldcs(src + i);
            }
#pragma unroll
            for (int j = 0; j < 4; j++) {
                if (!ok[j]) continue;
                const unsigned int e = (base + (unsigned int)(g * 4 + j) * BLK) * 4u;
                float vals[4] = {v[j].x, v[j].y, v[j].z, v[j].w};
#pragma unroll
                for (int k = 0; k < 4; k++) {
                    unsigned int key = f2key(vals[k]);
                    if (key >= KEY0) {
                        int p = atomicAdd(&lqn, 1);            // shared atomic
                        if (p < LQ)
                            lq[p] = ((unsigned long long)key << 32)
                                  | (unsigned int)(~(e + k));
                    }
                }
            }
        }
    }
    __syncthreads();

    // ---- one global reservation per block, coalesced copy-out ----
    {
        int m = lqn;
        if (m > LQ) {                       // adversarial overflow -> force fallback
            if (tid == 0) { g_ovf[b] = 1; }
            m = LQ;
        }
        if (tid == 0) gbase = atomicAdd(&g_cnt[b], m);
        __syncthreads();
        const int gb = gbase;
        for (int i = tid; i < m; i += BLK) {
            int pos = gb + i;
            if (pos < CAP) g_cand[b][pos] = lq[i];
            else if (tid == 0) {}           // cnt>CAP caught by finisher check
        }
    }
    // publish: bar.sync orders block stores before tid0's gpu-scope fence
    __syncthreads();

    // ---- last block of this batch becomes the finisher ----
    __shared__ int isLast;
    if (tid == 0) {
        __threadfence();
        isLast = (atomicAdd(&g_done[b], 1) == BLK_PER_B - 1);
    }
    __syncthreads();
    if (!isLast) return;
    if (tid == 0) __threadfence();
    __syncthreads();

    // ================= finisher phase =================
    __shared__ unsigned long long shcand[SHC];     // 16KB (aliased as fallback hist)
    __shared__ unsigned long long arr[ARRC];       // 8KB filtered set
    __shared__ unsigned long long topc[TOPK];
    __shared__ unsigned int hcnt[512];
    __shared__ unsigned int wsum[16];
    __shared__ unsigned int cut_s;
    __shared__ int nkeep, mode_s;
    __shared__ float thr_s;
    __shared__ int   qA[TOPK];
    __shared__ unsigned char mA[TOPK];

    int cnt = g_cnt[b];
    if (cnt < TOPK || cnt > CAP || g_ovf[b] != 0) {
        // ---- cold fallback (never taken on this data): exact recollect ----
        unsigned int* h4 = (unsigned int*)shcand;          // 4096 bins
        if (tid == 0) { g_cnt[b] = 0; g_ovf[b] = 0; }
        for (int t = tid; t < 4096; t += BLK) h4[t] = 0u;
        __syncthreads();
        const float* basep = cls + (size_t)b * NPB;
        for (int i = tid; i < NPB; i += BLK)
            atomicAdd(&h4[f2key(basep[i]) >> 20], 1u);
        __syncthreads();
        if (tid == 0) {
            unsigned int acc = 0; int cut = 0;
            for (int t = 4095; t >= 0; t--) { acc += h4[t]; if (acc >= TOPK) { cut = t; break; } }
            cut_s = (unsigned int)cut << 20;
        }
        __syncthreads();
        unsigned int ckf = cut_s;
        for (int i = tid; i < NPB; i += BLK) {
            unsigned int key = f2key(basep[i]);
            if (key >= ckf) {
                int pos = atomicAdd(&g_cnt[b], 1);
                if (pos < CAP)
                    g_cand[b][pos] = ((unsigned long long)key << 32)
                                   | (unsigned int)(~(unsigned int)i);
            }
        }
        __syncthreads();
        cnt = min(g_cnt[b], CAP);
        __syncthreads();
    }
    cnt = min(cnt, CAP);

    // cache candidates in shared (single global read)
    const unsigned long long* gc = g_cand[b];
    const bool cached = (cnt <= SHC);
    if (cached) {
        for (int i = tid; i < cnt; i += BLK) shcand[i] = gc[i];
        __syncthreads();
    }
    const unsigned long long* cand = cached ? (const unsigned long long*)shcand : gc;

    // ---- level 1: 512-bin cut on key>>23 ----
    hcnt[tid] = 0u;
    __syncthreads();
    for (int i = tid; i < cnt; i += BLK)
        atomicAdd(&hcnt[(unsigned int)(cand[i] >> (32 + 23))], 1u);
    __syncthreads();
    {
        unsigned int cv = hcnt[tid];
        unsigned int s = suffix_of(cv, wsum);
        if (s >= TOPK && s - cv < TOPK) cut_s = (unsigned int)tid;
    }
    __syncthreads();
    const unsigned int basek = cut_s << 23;
    __syncthreads();

    // ---- level 2: 512 bins of width 2^14 ----
    hcnt[tid] = 0u;
    __syncthreads();
    for (int i = tid; i < cnt; i += BLK) {
        unsigned int key = (unsigned int)(cand[i] >> 32);
        if (key >= basek) atomicAdd(&hcnt[min(511u, (key - basek) >> 14)], 1u);
    }
    __syncthreads();
    {
        unsigned int cv = hcnt[tid];
        unsigned int s = suffix_of(cv, wsum);
        if (s >= TOPK && s - cv < TOPK) cut_s = (unsigned int)tid;
    }
    __syncthreads();
    const unsigned int ck = basek + (cut_s << 14);

    // ---- filter >= ck into shared arr ----
    if (tid == 0) nkeep = 0;
    __syncthreads();
    for (int i = tid; i < cnt; i += BLK) {
        unsigned long long c = cand[i];
        if ((unsigned int)(c >> 32) >= ck) {
            int p = atomicAdd(&nkeep, 1);
            if (p < ARRC) arr[p] = c;
        }
    }
    __syncthreads();
    const int n = nkeep;

    // ---- exact rank-by-count (composites distinct -> unique ranks) ----
    if (tid < TOPK) topc[tid] = 0ULL;
    __syncthreads();
    if (n <= ARRC) {
        for (int i = tid; i < n; i += BLK) {
            unsigned long long c = arr[i];
            int rank = 0;
            for (int j = 0; j < n; j++) rank += (arr[j] > c);
            if (rank < TOPK) topc[rank] = c;
        }
    } else {
        // degenerate ties overflow (never on this data): rank over full list
        for (int i = tid; i < cnt; i += BLK) {
            unsigned long long c = cand[i];
            if ((unsigned int)(c >> 32) >= ck) {
                int rank = 0;
                for (int j = 0; j < cnt; j++) rank += (cand[j] > c);
                if (rank < TOPK) topc[rank] = c;
            }
        }
    }
    __syncthreads();

    if (tid == 0) {
        float f = key2f((unsigned int)(topc[0] >> 32));
        float maxs = 1.f / (1.f + expf(-f));
        int mode; float thr = 0.1f;
        if (maxs > 0.1f) mode = 0;
        else {
            float tmp = 0.1f; mode = 2;
            while (true) {
                tmp *= 0.9f;
                if (tmp < 0.01f) { mode = 2; break; }
                if (maxs >= tmp) { mode = 1; thr = tmp; break; }
            }
        }
        mode_s = mode; thr_s = thr;
    }
    __syncthreads();

    // output layout (float32, tuple order, C-contiguous each):
    float* oBox   = out;                       // [NB][TOPK][4]
    float* oScore = out + NB * TOPK * 4;       // [NB][TOPK]
    float* oLabel = oScore + NB * TOPK;        // [NB][TOPK]
    float* oPts   = oLabel + NB * TOPK;        // [NB][TOPK][NP][2]
    float* oMask  = oPts + NB * TOPK * NP * 2; // [NB][TOPK]

    // ---- stage 1: per-rank metadata + box/score/label/mask writes ----
    if (tid < TOPK) {
        const int r = tid;
        unsigned long long c = topc[r];
        const bool valid = (r < n);
        float score = 0.f, x1 = 0.f, y1 = 0.f, x2 = 0.f, y2 = 0.f;
        int label = 0, q = 0;
        bool mask = false;
        if (valid) {
            unsigned int key = (unsigned int)(c >> 32);
            unsigned int idx = ~(unsigned int)(c & 0xFFFFFFFFu);
            float f = key2f(key);
            score = 1.f / (1.f + expf(-f));
            label = (int)(idx % NC);
            q     = (int)(idx / NC);
            const float4 bb = __ldg((const float4*)(bbox + ((size_t)b * NQ + q) * 4));
            float cx = bb.x, cy = bb.y, w = bb.z, h = bb.w;
            x1 = (cx - w * 0.5f) * 30.f - 15.f;
            y1 = (cy - h * 0.5f) * 60.f - 30.f;
            x2 = (cx + w * 0.5f) * 30.f - 15.f;
            y2 = (cy + h * 0.5f) * 60.f - 30.f;
            bool rmask = x1 >= -20.f && y1 >= -35.f && x2 >= -20.f && y2 >= -35.f
                      && x1 <=  20.f && y1 <=  35.f && x2 <=  20.f && y2 <=  35.f;
            bool tm = (mode_s == 0) ? (score > 0.1f)
                    : (mode_s == 1) ? (score >= thr_s) : true;
            mask = rmask && tm;
        }
        qA[r] = q;
        mA[r] = mask ? 1 : 0;
        const size_t ob = (size_t)b * TOPK + r;
        ((float4*)oBox)[ob] = mask ? make_float4(x1, y1, x2, y2)
                                   : make_float4(0.f, 0.f, 0.f, 0.f);
        oScore[ob] = mask ? score : 0.f;
        oLabel[ob] = mask ? (float)label : 0.f;
        oMask[ob]  = mask ? 1.f : 0.f;
    }
    __syncthreads();

    // ---- stage 2: pts gather, vectorized and spread over all threads ----
    // 100 rows x 10 float4 chunks (40 floats per row)
    for (int t = tid; t < TOPK * 10; t += BLK) {
        const int r = t / 10, c4 = t % 10;
        const bool mk = mA[r] != 0;
        float4 o = make_float4(0.f, 0.f, 0.f, 0.f);
        if (mk) {
            const float4 v = __ldg((const float4*)(pts + ((size_t)b * NQ + qA[r]) * (NP * 2)) + c4);
            o.x = v.x * 30.f - 15.f;
            o.y = v.y * 60.f - 30.f;
            o.z = v.z * 30.f - 15.f;
            o.w = v.w * 60.f - 30.f;
        }
        ((float4*)oPts)[(size_t)b * TOPK * 10 + t] = o;
    }

    // ---- reset scratch for next graph replay ----
    __syncthreads();
    if (tid == 0) { g_cnt[b] = 0; g_done[b] = 0; g_ovf[b] = 0; }
}

extern "C" void kernel_launch(void* const* d_in, const int* in_sizes, int n_in,
                              void* d_out, int out_size) {
    const float* cls  = (const float*)d_in[0];   // [8,100000,10]
    const float* bbox = (const float*)d_in[1];   // [8,100000,4]
    const float* pts  = (const float*)d_in[2];   // [8,100000,20,2]
    float* out = (float*)d_out;

    dim3 grid(BLK_PER_B, NB);
    fused_k<<<grid, BLK>>>(cls, bbox, pts, out);
}

// round 15
// speedup vs baseline: 1.3433x; 1.0578x over previous
#include <cuda_runtime.h>
#include <cstdint>

#define NB 8
#define NQ 100000
#define NC 10
#define NPB (NQ*NC)          // 1,000,000 logits per batch
#define N4B (NPB/4)          // 250,000 float4 per batch
#define NP 20
#define TOPK 100
#define CAP 32768
#define KEY0 0xC0400000u     // sortable key of +3.0f (speculative threshold)
#define RAWTHR 0x40400000    // signed-int raw-bits threshold == +3.0f
#define BLK 512
#define F4_PER_BLK 4096      // BLK * 8
#define BLK_PER_B 62         // 62*4096 = 253952 >= 250000
#define LQ 256               // per-block local candidate queue (expected ~22)
#define SHC 2048             // shared candidate cache
#define ARRC 1024            // filtered set cap (fast rank path)

// ---- scratch (zero-initialized; finisher resets for graph replay) ----
__device__ int                g_cnt[NB];
__device__ int                g_done[NB];
__device__ int                g_ovf[NB];
__device__ unsigned long long g_cand[NB][CAP];

__device__ __forceinline__ unsigned int f2key(float f) {
    unsigned int u = __float_as_uint(f);
    return (u & 0x80000000u) ? ~u : (u | 0x80000000u);
}
__device__ __forceinline__ float key2f(unsigned int k) {
    unsigned int u = (k & 0x80000000u) ? (k & 0x7FFFFFFFu) : ~k;
    return __uint_as_float(u);
}
// candidate test: identical set to f2key(v) >= KEY0 (one signed ISETP)
__device__ __forceinline__ bool iscand(float v) {
    return (int)__float_as_uint(v) >= RAWTHR;
}

// suffix-inclusive count at bin tid, via warp shuffles. blockDim.x == 512.
__device__ __forceinline__ unsigned int suffix_of(unsigned int cntv, unsigned int* wsum) {
    const int tid = threadIdx.x, lane = tid & 31, wid = tid >> 5;
    unsigned int v = cntv;
#pragma unroll
    for (int off = 1; off < 32; off <<= 1) {
        unsigned int u = __shfl_down_sync(0xFFFFFFFFu, v, off);
        if (lane + off < 32) v += u;
    }
    if (lane == 0) wsum[wid] = v;   // warp total
    __syncthreads();
    if (tid < 16) {
        unsigned int w = wsum[tid];
#pragma unroll
        for (int off = 1; off < 16; off <<= 1) {
            unsigned int u = __shfl_down_sync(0xFFFFu, w, off);
            if (tid + off < 16) w += u;
        }
        wsum[tid] = w;              // inclusive suffix over warp totals
    }
    __syncthreads();
    return v + ((wid < 15) ? wsum[wid + 1] : 0u);
}

__global__ void __launch_bounds__(BLK) fused_k(const float* __restrict__ cls,
                                               const float* __restrict__ bbox,
                                               const float* __restrict__ pts,
                                               float* __restrict__ out) {
    const int b = blockIdx.y;
    const int tid = threadIdx.x;

    __shared__ unsigned long long lq[LQ];
    __shared__ int lqn;
    __shared__ int gbase;

    if (tid == 0) lqn = 0;
    __syncthreads();

    // ================= scan phase: 1-ISETP candidate test =================
    {
        const float4* src = (const float4*)(cls + (size_t)b * NPB);
        const unsigned int base = blockIdx.x * F4_PER_BLK + tid;
        const bool full = (blockIdx.x + 1) * F4_PER_BLK <= N4B;   // uniform

        if (full) {
#pragma unroll
            for (int g = 0; g < 2; g++) {
                float4 v[4];
#pragma unroll
                for (int j = 0; j < 4; j++)
                    v[j] = __ldcs(src + base + (unsigned int)(g * 4 + j) * BLK);
#pragma unroll
                for (int j = 0; j < 4; j++) {
                    if (iscand(v[j].x) | iscand(v[j].y) | iscand(v[j].z) | iscand(v[j].w)) {
                        const unsigned int e = (base + (unsigned int)(g * 4 + j) * BLK) * 4u;
                        float vals[4] = {v[j].x, v[j].y, v[j].z, v[j].w};
#pragma unroll
                        for (int k = 0; k < 4; k++) {
                            if (iscand(vals[k])) {
                                int p = atomicAdd(&lqn, 1);
                                if (p < LQ)
                                    lq[p] = ((unsigned long long)f2key(vals[k]) << 32)
                                          | (unsigned int)(~(e + k));
                            }
                        }
                    }
                }
            }
        } else {
#pragma unroll
            for (int g = 0; g < 8; g++) {
                unsigned int i = base + (unsigned int)g * BLK;
                if (i >= N4B) continue;
                float4 v = __ldcs(src + i);
                if (iscand(v.x) | iscand(v.y) | iscand(v.z) | iscand(v.w)) {
                    const unsigned int e = i * 4u;
                    float vals[4] = {v.x, v.y, v.z, v.w};
#pragma unroll
                    for (int k = 0; k < 4; k++) {
                        if (iscand(vals[k])) {
                            int p = atomicAdd(&lqn, 1);
                            if (p < LQ)
                                lq[p] = ((unsigned long long)f2key(vals[k]) << 32)
                                      | (unsigned int)(~(e + k));
                        }
                    }
                }
            }
        }
    }
    __syncthreads();

    // ---- one global reservation per block, coalesced copy-out ----
    {
        int m = lqn;
        if (m > LQ) {                       // adversarial overflow -> force fallback
            if (tid == 0) g_ovf[b] = 1;
            m = LQ;
        }
        if (tid == 0) gbase = atomicAdd(&g_cnt[b], m);
        __syncthreads();
        const int gb = gbase;
        for (int i = tid; i < m; i += BLK) {
            int pos = gb + i;
            if (pos < CAP) g_cand[b][pos] = lq[i];
        }
    }
    __syncthreads();

    // ---- last block of this batch becomes the finisher ----
    __shared__ int isLast;
    if (tid == 0) {
        __threadfence();
        isLast = (atomicAdd(&g_done[b], 1) == BLK_PER_B - 1);
    }
    __syncthreads();
    if (!isLast) return;
    if (tid == 0) __threadfence();
    __syncthreads();

    // ================= finisher phase =================
    __shared__ unsigned long long shcand[SHC];     // 16KB (aliased as fallback hist)
    __shared__ unsigned long long arr[ARRC];       // 8KB filtered set
    __shared__ unsigned long long topc[TOPK];
    __shared__ unsigned int hcnt[512];
    __shared__ unsigned int wsum[16];
    __shared__ unsigned int cut_s;
    __shared__ int nkeep, mode_s;
    __shared__ float thr_s;
    __shared__ int   qA[TOPK];
    __shared__ unsigned char mA[TOPK];

    int cnt = g_cnt[b];
    if (cnt < TOPK || cnt > CAP || g_ovf[b] != 0) {
        // ---- cold fallback (never taken on this data): exact recollect ----
        unsigned int* h4 = (unsigned int*)shcand;          // 4096 bins
        if (tid == 0) { g_cnt[b] = 0; g_ovf[b] = 0; }
        for (int t = tid; t < 4096; t += BLK) h4[t] = 0u;
        __syncthreads();
        const float* basep = cls + (size_t)b * NPB;
        for (int i = tid; i < NPB; i += BLK)
            atomicAdd(&h4[f2key(basep[i]) >> 20], 1u);
        __syncthreads();
        if (tid == 0) {
            unsigned int acc = 0; int cut = 0;
            for (int t = 4095; t >= 0; t--) { acc += h4[t]; if (acc >= TOPK) { cut = t; break; } }
            cut_s = (unsigned int)cut << 20;
        }
        __syncthreads();
        unsigned int ckf = cut_s;
        for (int i = tid; i < NPB; i += BLK) {
            unsigned int key = f2key(basep[i]);
            if (key >= ckf) {
                int pos = atomicAdd(&g_cnt[b], 1);
                if (pos < CAP)
                    g_cand[b][pos] = ((unsigned long long)key << 32)
                                   | (unsigned int)(~(unsigned int)i);
            }
        }
        __syncthreads();
        cnt = min(g_cnt[b], CAP);
        __syncthreads();
    }
    cnt = min(cnt, CAP);

    // cache candidates in shared (single global read)
    const unsigned long long* gc = g_cand[b];
    const bool cached = (cnt <= SHC);
    if (cached) {
        for (int i = tid; i < cnt; i += BLK) shcand[i] = gc[i];
        __syncthreads();
    }
    const unsigned long long* cand = cached ? (const unsigned long long*)shcand : gc;

    // ---- level 1: 512-bin cut on key>>23 ----
    hcnt[tid] = 0u;
    __syncthreads();
    for (int i = tid; i < cnt; i += BLK)
        atomicAdd(&hcnt[(unsigned int)(cand[i] >> (32 + 23))], 1u);
    __syncthreads();
    {
        unsigned int cv = hcnt[tid];
        unsigned int s = suffix_of(cv, wsum);
        if (s >= TOPK && s - cv < TOPK) cut_s = (unsigned int)tid;
    }
    __syncthreads();
    const unsigned int basek = cut_s << 23;
    __syncthreads();

    // ---- level 2: 512 bins of width 2^14 ----
    hcnt[tid] = 0u;
    __syncthreads();
    for (int i = tid; i < cnt; i += BLK) {
        unsigned int key = (unsigned int)(cand[i] >> 32);
        if (key >= basek) atomicAdd(&hcnt[min(511u, (key - basek) >> 14)], 1u);
    }
    __syncthreads();
    {
        unsigned int cv = hcnt[tid];
        unsigned int s = suffix_of(cv, wsum);
        if (s >= TOPK && s - cv < TOPK) cut_s = (unsigned int)tid;
    }
    __syncthreads();
    const unsigned int ck = basek + (cut_s << 14);

    // ---- filter >= ck into shared arr ----
    if (tid == 0) nkeep = 0;
    __syncthreads();
    for (int i = tid; i < cnt; i += BLK) {
        unsigned long long c = cand[i];
        if ((unsigned int)(c >> 32) >= ck) {
            int p = atomicAdd(&nkeep, 1);
            if (p < ARRC) arr[p] = c;
        }
    }
    __syncthreads();
    const int n = nkeep;

    // ---- exact rank-by-count (composites distinct -> unique ranks) ----
    if (tid < TOPK) topc[tid] = 0ULL;
    __syncthreads();
    if (n <= ARRC) {
        for (int i = tid; i < n; i += BLK) {
            unsigned long long c = arr[i];
            int rank = 0;
            for (int j = 0; j < n; j++) rank += (arr[j] > c);
            if (rank < TOPK) topc[rank] = c;
        }
    } else {
        for (int i = tid; i < cnt; i += BLK) {
            unsigned long long c = cand[i];
            if ((unsigned int)(c >> 32) >= ck) {
                int rank = 0;
                for (int j = 0; j < cnt; j++) rank += (cand[j] > c);
                if (rank < TOPK) topc[rank] = c;
            }
        }
    }
    __syncthreads();

    if (tid == 0) {
        float f = key2f((unsigned int)(topc[0] >> 32));
        float maxs = 1.f / (1.f + expf(-f));
        int mode; float thr = 0.1f;
        if (maxs > 0.1f) mode = 0;
        else {
            float tmp = 0.1f; mode = 2;
            while (true) {
                tmp *= 0.9f;
                if (tmp < 0.01f) { mode = 2; break; }
                if (maxs >= tmp) { mode = 1; thr = tmp; break; }
            }
        }
        mode_s = mode; thr_s = thr;
    }
    __syncthreads();

    // output layout (float32, tuple order, C-contiguous each):
    float* oBox   = out;                       // [NB][TOPK][4]
    float* oScore = out + NB * TOPK * 4;       // [NB][TOPK]
    float* oLabel = oScore + NB * TOPK;        // [NB][TOPK]
    float* oPts   = oLabel + NB * TOPK;        // [NB][TOPK][NP][2]
    float* oMask  = oPts + NB * TOPK * NP * 2; // [NB][TOPK]

    // ---- stage 1: per-rank metadata + box/score/label/mask writes ----
    if (tid < TOPK) {
        const int r = tid;
        unsigned long long c = topc[r];
        const bool valid = (r < n);
        float score = 0.f, x1 = 0.f, y1 = 0.f, x2 = 0.f, y2 = 0.f;
        int label = 0, q = 0;
        bool mask = false;
        if (valid) {
            unsigned int key = (unsigned int)(c >> 32);
            unsigned int idx = ~(unsigned int)(c & 0xFFFFFFFFu);
            float f = key2f(key);
            score = 1.f / (1.f + expf(-f));
            label = (int)(idx % NC);
            q     = (int)(idx / NC);
            const float4 bb = __ldg((const float4*)(bbox + ((size_t)b * NQ + q) * 4));
            float cx = bb.x, cy = bb.y, w = bb.z, h = bb.w;
            x1 = (cx - w * 0.5f) * 30.f - 15.f;
            y1 = (cy - h * 0.5f) * 60.f - 30.f;
            x2 = (cx + w * 0.5f) * 30.f - 15.f;
            y2 = (cy + h * 0.5f) * 60.f - 30.f;
            bool rmask = x1 >= -20.f && y1 >= -35.f && x2 >= -20.f && y2 >= -35.f
                      && x1 <=  20.f && y1 <=  35.f && x2 <=  20.f && y2 <=  35.f;
            bool tm = (mode_s == 0) ? (score > 0.1f)
                    : (mode_s == 1) ? (score >= thr_s) : true;
            mask = rmask && tm;
        }
        qA[r] = q;
        mA[r] = mask ? 1 : 0;
        const size_t ob = (size_t)b * TOPK + r;
        ((float4*)oBox)[ob] = mask ? make_float4(x1, y1, x2, y2)
                                   : make_float4(0.f, 0.f, 0.f, 0.f);
        oScore[ob] = mask ? score : 0.f;
        oLabel[ob] = mask ? (float)label : 0.f;
        oMask[ob]  = mask ? 1.f : 0.f;
    }
    __syncthreads();

    // ---- stage 2: pts gather, vectorized and spread over all threads ----
    for (int t = tid; t < TOPK * 10; t += BLK) {
        const int r = t / 10, c4 = t % 10;
        const bool mk = mA[r] != 0;
        float4 o = make_float4(0.f, 0.f, 0.f, 0.f);
        if (mk) {
            const float4 v = __ldg((const float4*)(pts + ((size_t)b * NQ + qA[r]) * (NP * 2)) + c4);
            o.x = v.x * 30.f - 15.f;
            o.y = v.y * 60.f - 30.f;
            o.z = v.z * 30.f - 15.f;
            o.w = v.w * 60.f - 30.f;
        }
        ((float4*)oPts)[(size_t)b * TOPK * 10 + t] = o;
    }

    // ---- reset scratch for next graph replay ----
    __syncthreads();
    if (tid == 0) { g_cnt[b] = 0; g_done[b] = 0; g_ovf[b] = 0; }
}

extern "C" void kernel_launch(void* const* d_in, const int* in_sizes, int n_in,
                              void* d_out, int out_size) {
    const float* cls  = (const float*)d_in[0];   // [8,100000,10]
    const float* bbox = (const float*)d_in[1];   // [8,100000,4]
    const float* pts  = (const float*)d_in[2];   // [8,100000,20,2]
    float* out = (float*)d_out;

    dim3 grid(BLK_PER_B, NB);
    fused_k<<<grid, BLK>>>(cls, bbox, pts, out);
}

// round 16
// speedup vs baseline: 1.4008x; 1.0428x over previous
#include <cuda_runtime.h>
#include <cstdint>

#define NB 8
#define NQ 100000
#define NC 10
#define NPB (NQ*NC)          // 1,000,000 logits per batch
#define N4B (NPB/4)          // 250,000 float4 per batch
#define NP 20
#define TOPK 100
#define CAP 32768
#define RAWTHR 0x40600000    // signed raw-bits threshold == +3.5f
#define KEY0 0xC0600000u     // sortable key of +3.5f
#define BLK 512
#define F4_PER_BLK 4096      // BLK * 8
#define BLK_PER_B 62         // 62*4096 = 253952 >= 250000
#define LQ 256               // per-block local queue (expected ~4)
#define SHC 2048             // shared candidate cache (cold path)
#define ARRC 1024            // direct-rank cap

// ---- scratch (zero-initialized; finisher resets for graph replay) ----
__device__ int                g_cnt[NB];
__device__ int                g_done[NB];
__device__ int                g_ovf[NB];
__device__ unsigned long long g_cand[NB][CAP];

__device__ __forceinline__ unsigned int f2key(float f) {
    unsigned int u = __float_as_uint(f);
    return (u & 0x80000000u) ? ~u : (u | 0x80000000u);
}
__device__ __forceinline__ float key2f(unsigned int k) {
    unsigned int u = (k & 0x80000000u) ? (k & 0x7FFFFFFFu) : ~k;
    return __uint_as_float(u);
}
// identical set to f2key(v) >= KEY0, one signed ISETP
__device__ __forceinline__ bool iscand(float v) {
    return (int)__float_as_uint(v) >= RAWTHR;
}

// suffix-inclusive count at bin tid, via warp shuffles. blockDim.x == 512.
__device__ __forceinline__ unsigned int suffix_of(unsigned int cntv, unsigned int* wsum) {
    const int tid = threadIdx.x, lane = tid & 31, wid = tid >> 5;
    unsigned int v = cntv;
#pragma unroll
    for (int off = 1; off < 32; off <<= 1) {
        unsigned int u = __shfl_down_sync(0xFFFFFFFFu, v, off);
        if (lane + off < 32) v += u;
    }
    if (lane == 0) wsum[wid] = v;
    __syncthreads();
    if (tid < 16) {
        unsigned int w = wsum[tid];
#pragma unroll
        for (int off = 1; off < 16; off <<= 1) {
            unsigned int u = __shfl_down_sync(0xFFFFu, w, off);
            if (tid + off < 16) w += u;
        }
        wsum[tid] = w;
    }
    __syncthreads();
    return v + ((wid < 15) ? wsum[wid + 1] : 0u);
}

__global__ void __launch_bounds__(BLK) fused_k(const float* __restrict__ cls,
                                               const float* __restrict__ bbox,
                                               const float* __restrict__ pts,
                                               float* __restrict__ out) {
    const int b = blockIdx.y;
    const int tid = threadIdx.x;

    __shared__ unsigned long long lq[LQ];
    __shared__ int lqn;
    __shared__ int gbase;

    if (tid == 0) lqn = 0;
    __syncthreads();

    // ================= scan phase =================
    {
        const float4* src = (const float4*)(cls + (size_t)b * NPB);
        const unsigned int base = blockIdx.x * F4_PER_BLK + tid;
        const bool full = (blockIdx.x + 1) * F4_PER_BLK <= N4B;   // uniform

        if (full) {
#pragma unroll
            for (int g = 0; g < 2; g++) {
                float4 v[4];
#pragma unroll
                for (int j = 0; j < 4; j++)
                    v[j] = __ldcs(src + base + (unsigned int)(g * 4 + j) * BLK);
#pragma unroll
                for (int j = 0; j < 4; j++) {
                    if (iscand(v[j].x) | iscand(v[j].y) | iscand(v[j].z) | iscand(v[j].w)) {
                        const unsigned int e = (base + (unsigned int)(g * 4 + j) * BLK) * 4u;
                        float vals[4] = {v[j].x, v[j].y, v[j].z, v[j].w};
#pragma unroll
                        for (int k = 0; k < 4; k++) {
                            if (iscand(vals[k])) {
                                int p = atomicAdd(&lqn, 1);
                                if (p < LQ)
                                    lq[p] = ((unsigned long long)f2key(vals[k]) << 32)
                                          | (unsigned int)(~(e + k));
                            }
                        }
                    }
                }
            }
        } else {
#pragma unroll
            for (int g = 0; g < 8; g++) {
                unsigned int i = base + (unsigned int)g * BLK;
                if (i >= N4B) continue;
                float4 v = __ldcs(src + i);
                if (iscand(v.x) | iscand(v.y) | iscand(v.z) | iscand(v.w)) {
                    const unsigned int e = i * 4u;
                    float vals[4] = {v.x, v.y, v.z, v.w};
#pragma unroll
                    for (int k = 0; k < 4; k++) {
                        if (iscand(vals[k])) {
                            int p = atomicAdd(&lqn, 1);
                            if (p < LQ)
                                lq[p] = ((unsigned long long)f2key(vals[k]) << 32)
                                      | (unsigned int)(~(e + k));
                        }
                    }
                }
            }
        }
    }
    __syncthreads();

    // ---- one global reservation per block, coalesced copy-out ----
    {
        int m = lqn;
        if (m > LQ) {                       // adversarial overflow -> force fallback
            if (tid == 0) g_ovf[b] = 1;
            m = LQ;
        }
        if (tid == 0) gbase = atomicAdd(&g_cnt[b], m);
        __syncthreads();
        const int gb = gbase;
        for (int i = tid; i < m; i += BLK) {
            int pos = gb + i;
            if (pos < CAP) g_cand[b][pos] = lq[i];
        }
    }
    __syncthreads();

    // ---- last block of this batch becomes the finisher ----
    __shared__ int isLast;
    if (tid == 0) {
        __threadfence();
        isLast = (atomicAdd(&g_done[b], 1) == BLK_PER_B - 1);
    }
    __syncthreads();
    if (!isLast) return;
    if (tid == 0) __threadfence();
    __syncthreads();

    // ================= finisher phase =================
    __shared__ unsigned long long shcand[SHC];     // 16KB (cold paths / fallback hist)
    __shared__ unsigned long long arr[ARRC];       // 8KB rank set
    __shared__ unsigned long long topc[TOPK];
    __shared__ unsigned int hcnt[512];
    __shared__ unsigned int wsum[16];
    __shared__ unsigned int cut_s;
    __shared__ int nkeep, mode_s;
    __shared__ float thr_s;
    __shared__ int   qA[TOPK];
    __shared__ unsigned char mA[TOPK];

    int cnt = g_cnt[b];
    if (cnt < TOPK || cnt > CAP || g_ovf[b] != 0) {
        // ---- cold fallback (never taken on this data): exact recollect ----
        unsigned int* h4 = (unsigned int*)shcand;          // 4096 bins
        if (tid == 0) { g_cnt[b] = 0; g_ovf[b] = 0; }
        for (int t = tid; t < 4096; t += BLK) h4[t] = 0u;
        __syncthreads();
        const float* basep = cls + (size_t)b * NPB;
        for (int i = tid; i < NPB; i += BLK)
            atomicAdd(&h4[f2key(basep[i]) >> 20], 1u);
        __syncthreads();
        if (tid == 0) {
            unsigned int acc = 0; int cut = 0;
            for (int t = 4095; t >= 0; t--) { acc += h4[t]; if (acc >= TOPK) { cut = t; break; } }
            cut_s = (unsigned int)cut << 20;
        }
        __syncthreads();
        unsigned int ckf = cut_s;
        for (int i = tid; i < NPB; i += BLK) {
            unsigned int key = f2key(basep[i]);
            if (key >= ckf) {
                int pos = atomicAdd(&g_cnt[b], 1);
                if (pos < CAP)
                    g_cand[b][pos] = ((unsigned long long)key << 32)
                                   | (unsigned int)(~(unsigned int)i);
            }
        }
        __syncthreads();
        cnt = min(g_cnt[b], CAP);
        __syncthreads();
    }
    cnt = min(cnt, CAP);

    int n;   // rank-set size in arr
    if (cnt <= ARRC) {
        // ======== hot path: direct rank set, NO histograms ========
        for (int i = tid; i < cnt; i += BLK) arr[i] = g_cand[b][i];
        n = cnt;
        __syncthreads();
    } else {
        // ======== cold path: two-level cut (as R15) ========
        const unsigned long long* gc = g_cand[b];
        const bool cached = (cnt <= SHC);
        if (cached) {
            for (int i = tid; i < cnt; i += BLK) shcand[i] = gc[i];
            __syncthreads();
        }
        const unsigned long long* cand = cached ? (const unsigned long long*)shcand : gc;

        hcnt[tid] = 0u;
        __syncthreads();
        for (int i = tid; i < cnt; i += BLK)
            atomicAdd(&hcnt[(unsigned int)(cand[i] >> (32 + 23))], 1u);
        __syncthreads();
        {
            unsigned int cv = hcnt[tid];
            unsigned int s = suffix_of(cv, wsum);
            if (s >= TOPK && s - cv < TOPK) cut_s = (unsigned int)tid;
        }
        __syncthreads();
        const unsigned int basek = cut_s << 23;
        __syncthreads();

        hcnt[tid] = 0u;
        __syncthreads();
        for (int i = tid; i < cnt; i += BLK) {
            unsigned int key = (unsigned int)(cand[i] >> 32);
            if (key >= basek) atomicAdd(&hcnt[min(511u, (key - basek) >> 14)], 1u);
        }
        __syncthreads();
        {
            unsigned int cv = hcnt[tid];
            unsigned int s = suffix_of(cv, wsum);
            if (s >= TOPK && s - cv < TOPK) cut_s = (unsigned int)tid;
        }
        __syncthreads();
        const unsigned int ck = basek + (cut_s << 14);

        if (tid == 0) nkeep = 0;
        __syncthreads();
        for (int i = tid; i < cnt; i += BLK) {
            unsigned long long c = cand[i];
            if ((unsigned int)(c >> 32) >= ck) {
                int p = atomicAdd(&nkeep, 1);
                if (p < ARRC) arr[p] = c;
            }
        }
        __syncthreads();
        n = nkeep;
        if (n > ARRC) {
            // degenerate ties overflow: exact rank over full candidate list
            if (tid < TOPK) topc[tid] = 0ULL;
            __syncthreads();
            for (int i = tid; i < cnt; i += BLK) {
                unsigned long long c = cand[i];
                if ((unsigned int)(c >> 32) >= ck) {
                    int rank = 0;
                    for (int j = 0; j < cnt; j++) rank += (cand[j] > c);
                    if (rank < TOPK) topc[rank] = c;
                }
            }
            n = ARRC;   // topc fully populated; arr-based rank below skipped
            goto ranked;
        }
    }

    // ---- exact rank-by-count over arr (composites distinct -> unique ranks) ----
    if (tid < TOPK) topc[tid] = 0ULL;
    __syncthreads();
    for (int i = tid; i < n; i += BLK) {
        unsigned long long c = arr[i];
        int rank = 0;
        for (int j = 0; j < n; j++) rank += (arr[j] > c);
        if (rank < TOPK) topc[rank] = c;
    }
ranked:
    __syncthreads();

    if (tid == 0) {
        float f = key2f((unsigned int)(topc[0] >> 32));
        float maxs = 1.f / (1.f + expf(-f));
        int mode; float thr = 0.1f;
        if (maxs > 0.1f) mode = 0;
        else {
            float tmp = 0.1f; mode = 2;
            while (true) {
                tmp *= 0.9f;
                if (tmp < 0.01f) { mode = 2; break; }
                if (maxs >= tmp) { mode = 1; thr = tmp; break; }
            }
        }
        mode_s = mode; thr_s = thr;
    }
    __syncthreads();

    // output layout (float32, tuple order, C-contiguous each):
    float* oBox   = out;                       // [NB][TOPK][4]
    float* oScore = out + NB * TOPK * 4;       // [NB][TOPK]
    float* oLabel = oScore + NB * TOPK;        // [NB][TOPK]
    float* oPts   = oLabel + NB * TOPK;        // [NB][TOPK][NP][2]
    float* oMask  = oPts + NB * TOPK * NP * 2; // [NB][TOPK]

    const int nv = min(n, TOPK);               // valid ranks

    // ---- stage 1: per-rank metadata + box/score/label/mask writes ----
    if (tid < TOPK) {
        const int r = tid;
        unsigned long long c = topc[r];
        const bool valid = (r < nv);
        float score = 0.f, x1 = 0.f, y1 = 0.f, x2 = 0.f, y2 = 0.f;
        int label = 0, q = 0;
        bool mask = false;
        if (valid) {
            unsigned int key = (unsigned int)(c >> 32);
            unsigned int idx = ~(unsigned int)(c & 0xFFFFFFFFu);
            float f = key2f(key);
            score = 1.f / (1.f + expf(-f));
            label = (int)(idx % NC);
            q     = (int)(idx / NC);
            const float4 bb = __ldg((const float4*)(bbox + ((size_t)b * NQ + q) * 4));
            float cx = bb.x, cy = bb.y, w = bb.z, h = bb.w;
            x1 = (cx - w * 0.5f) * 30.f - 15.f;
            y1 = (cy - h * 0.5f) * 60.f - 30.f;
            x2 = (cx + w * 0.5f) * 30.f - 15.f;
            y2 = (cy + h * 0.5f) * 60.f - 30.f;
            bool rmask = x1 >= -20.f && y1 >= -35.f && x2 >= -20.f && y2 >= -35.f
                      && x1 <=  20.f && y1 <=  35.f && x2 <=  20.f && y2 <=  35.f;
            bool tm = (mode_s == 0) ? (score > 0.1f)
                    : (mode_s == 1) ? (score >= thr_s) : true;
            mask = rmask && tm;
        }
        qA[r] = q;
        mA[r] = mask ? 1 : 0;
        const size_t ob = (size_t)b * TOPK + r;
        ((float4*)oBox)[ob] = mask ? make_float4(x1, y1, x2, y2)
                                   : make_float4(0.f, 0.f, 0.f, 0.f);
        oScore[ob] = mask ? score : 0.f;
        oLabel[ob] = mask ? (float)label : 0.f;
        oMask[ob]  = mask ? 1.f : 0.f;
    }
    __syncthreads();

    // ---- stage 2: pts gather, vectorized, spread over all threads ----
    for (int t = tid; t < TOPK * 10; t += BLK) {
        const int r = t / 10, c4 = t % 10;
        const bool mk = mA[r] != 0;
        float4 o = make_float4(0.f, 0.f, 0.f, 0.f);
        if (mk) {
            const float4 v = __ldg((const float4*)(pts + ((size_t)b * NQ + qA[r]) * (NP * 2)) + c4);
            o.x = v.x * 30.f - 15.f;
            o.y = v.y * 60.f - 30.f;
            o.z = v.z * 30.f - 15.f;
            o.w = v.w * 60.f - 30.f;
        }
        ((float4*)oPts)[(size_t)b * TOPK * 10 + t] = o;
    }

    // ---- reset scratch for next graph replay ----
    __syncthreads();
    if (tid == 0) { g_cnt[b] = 0; g_done[b] = 0; g_ovf[b] = 0; }
}

extern "C" void kernel_launch(void* const* d_in, const int* in_sizes, int n_in,
                              void* d_out, int out_size) {
    const float* cls  = (const float*)d_in[0];   // [8,100000,10]
    const float* bbox = (const float*)d_in[1];   // [8,100000,4]
    const float* pts  = (const float*)d_in[2];   // [8,100000,20,2]
    float* out = (float*)d_out;

    dim3 grid(BLK_PER_B, NB);
    fused_k<<<grid, BLK>>>(cls, bbox, pts, out);
}